// round 1
// baseline (speedup 1.0000x reference)
#include <cuda_runtime.h>

#define NN    100000
#define EMAX  1700000
#define INC   128
#define H1DIM 64     // HEADS*HID
#define HEADS 8
#define HID   8
#define OUTC  40

// ---- scratch (static __device__ globals; no allocation allowed) ----
__device__ float g_h1[NN * H1DIM];          // layer-1 features  [N,64]
__device__ float g_as1[NN * HEADS];         // alpha_src per node/head
__device__ float g_ad1[NN * HEADS];
__device__ float g_denom1[NN * HEADS];      // softmax denominators
__device__ float g_ex1[(size_t)EMAX * HEADS];  // per-edge exp(e) (54MB)
__device__ float g_out1[NN * H1DIM];        // aggregated layer-1 out (+b1 baked)
__device__ float g_act1[NN * H1DIM];        // ELU(out1)
__device__ float g_h2[NN * OUTC];           // layer-2 features [N,40]
__device__ float g_as2[NN];
__device__ float g_ad2[NN];
__device__ float g_denom2[NN];
__device__ float g_ex2[EMAX];

// ---- init: bake biases into accumulators, zero denominators ----
__global__ void k_init(float* __restrict__ dout,
                       const float* __restrict__ b1,
                       const float* __restrict__ b2) {
    int id = blockIdx.x * blockDim.x + threadIdx.x;
    if (id < NN * H1DIM) g_out1[id] = b1[id & 63];
    if (id < NN * HEADS) g_denom1[id] = 0.f;
    if (id < NN)         g_denom2[id] = 0.f;
    if (id < NN * OUTC)  dout[id] = b2[id % OUTC];
}

// ---- layer 1 GEMM: h1 = x @ W1^T, fused attention dot products ----
// block = 256 threads = 4 nodes x 64 features
__global__ void k_gemm1(const float* __restrict__ x,
                        const float* __restrict__ W1,
                        const float* __restrict__ as_w,   // att_src1 flat[64]
                        const float* __restrict__ ad_w) { // att_dst1 flat[64]
    __shared__ float xs[4][INC];
    int nb = blockIdx.x * 4;
    int t  = threadIdx.x;

    for (int i = t; i < 4 * INC; i += 256) {
        int node = nb + (i >> 7);
        xs[i >> 7][i & 127] = (node < NN) ? x[node * INC + (i & 127)] : 0.f;
    }
    __syncthreads();

    int local = t >> 6;          // node within block (0..3)
    int f     = t & 63;          // output feature = head*8 + ch
    int node  = nb + local;

    float acc = 0.f;
    const float* wrow = W1 + f * INC;
    #pragma unroll 8
    for (int k = 0; k < INC; k++) acc += xs[local][k] * wrow[k];

    // attention partials: att flat index == f (head*HID + ch)
    float vs = acc * as_w[f];
    float vd = acc * ad_w[f];
    #pragma unroll
    for (int off = 1; off < HID; off <<= 1) {
        vs += __shfl_xor_sync(0xffffffffu, vs, off);
        vd += __shfl_xor_sync(0xffffffffu, vd, off);
    }
    if (node < NN) {
        g_h1[node * H1DIM + f] = acc;
        if ((f & 7) == 0) {
            g_as1[node * HEADS + (f >> 3)] = vs;
            g_ad1[node * HEADS + (f >> 3)] = vd;
        }
    }
}

// ---- layer 1 edge pass: ex = exp(lrelu(a_s[src]+a_d[dst])), denom += ex ----
__global__ void k_edge1(const int* __restrict__ src, const int* __restrict__ dst, int nE) {
    int id = blockIdx.x * blockDim.x + threadIdx.x;
    if (id >= nE * HEADS) return;
    int e = id >> 3, h = id & 7;
    int s = src[e], d = dst[e];
    float v = g_as1[s * HEADS + h] + g_ad1[d * HEADS + h];
    v = (v > 0.f) ? v : 0.2f * v;
    float ex = __expf(v);          // max-shift cancels algebraically; logits are O(1)
    g_ex1[id] = ex;
    atomicAdd(&g_denom1[d * HEADS + h], ex);
}

// ---- layer 1 scatter: out1[dst] += alpha * h1[src]  (8 ch per thread) ----
__global__ void k_scat1(const int* __restrict__ src, const int* __restrict__ dst, int nE) {
    int id = blockIdx.x * blockDim.x + threadIdx.x;
    if (id >= nE * HEADS) return;
    int e = id >> 3, h = id & 7;
    int s = src[e], d = dst[e];
    float alpha = g_ex1[id] / g_denom1[d * HEADS + h];
    const float4* hv = (const float4*)(g_h1 + s * H1DIM + h * HID);
    float4 m0 = hv[0], m1 = hv[1];
    float* o = g_out1 + d * H1DIM + h * HID;
    atomicAdd(o + 0, m0.x * alpha); atomicAdd(o + 1, m0.y * alpha);
    atomicAdd(o + 2, m0.z * alpha); atomicAdd(o + 3, m0.w * alpha);
    atomicAdd(o + 4, m1.x * alpha); atomicAdd(o + 5, m1.y * alpha);
    atomicAdd(o + 6, m1.z * alpha); atomicAdd(o + 7, m1.w * alpha);
}

// ---- ELU ----
__global__ void k_elu() {
    int id = blockIdx.x * blockDim.x + threadIdx.x;
    if (id >= NN * H1DIM) return;
    float v = g_out1[id];
    g_act1[id] = (v > 0.f) ? v : expm1f(v);
}

// ---- layer 2 GEMM: h2 = act1 @ W2^T   (block = 320 = 8 nodes x 40 feats) ----
__global__ void k_gemm2(const float* __restrict__ W2) {
    __shared__ float w[OUTC * H1DIM];   // 10KB
    __shared__ float a[8][H1DIM];
    int t = threadIdx.x;
    for (int i = t; i < OUTC * H1DIM; i += 320) w[i] = W2[i];
    int nb = blockIdx.x * 8;
    for (int i = t; i < 8 * H1DIM; i += 320) {
        int node = nb + (i >> 6);
        a[i >> 6][i & 63] = (node < NN) ? g_act1[node * H1DIM + (i & 63)] : 0.f;
    }
    __syncthreads();
    int local = t / OUTC, f = t - local * OUTC;
    int node = nb + local;
    if (node < NN) {
        float acc = 0.f;
        #pragma unroll
        for (int k = 0; k < H1DIM; k++) acc += a[local][k] * w[f * H1DIM + k];
        g_h2[node * OUTC + f] = acc;
    }
}

// ---- layer 2 attention dots ----
__global__ void k_att2(const float* __restrict__ as_w, const float* __restrict__ ad_w) {
    int n = blockIdx.x * blockDim.x + threadIdx.x;
    if (n >= NN) return;
    const float* hp = g_h2 + n * OUTC;
    float s = 0.f, d = 0.f;
    #pragma unroll
    for (int i = 0; i < OUTC; i++) { float v = hp[i]; s += v * as_w[i]; d += v * ad_w[i]; }
    g_as2[n] = s;
    g_ad2[n] = d;
}

// ---- layer 2 edge pass ----
__global__ void k_edge2(const int* __restrict__ src, const int* __restrict__ dst, int nE) {
    int e = blockIdx.x * blockDim.x + threadIdx.x;
    if (e >= nE) return;
    int s = src[e], d = dst[e];
    float v = g_as2[s] + g_ad2[d];
    v = (v > 0.f) ? v : 0.2f * v;
    float ex = __expf(v);
    g_ex2[e] = ex;
    atomicAdd(&g_denom2[d], ex);
}

// ---- layer 2 scatter: out[dst,c] += alpha * h2[src,c] ----
__global__ void k_scat2(const int* __restrict__ src, const int* __restrict__ dst,
                        int nE, float* __restrict__ dout) {
    int id = blockIdx.x * blockDim.x + threadIdx.x;
    if (id >= nE * OUTC) return;
    int e = id / OUTC, c = id - e * OUTC;
    int s = src[e], d = dst[e];
    float alpha = g_ex2[e] / g_denom2[d];
    atomicAdd(dout + d * OUTC + c, g_h2[s * OUTC + c] * alpha);
}

extern "C" void kernel_launch(void* const* d_in, const int* in_sizes, int n_in,
                              void* d_out, int out_size) {
    const float* x   = (const float*)d_in[0];
    const int*   ei  = (const int*)  d_in[1];
    const float* W1  = (const float*)d_in[2];
    const float* as1 = (const float*)d_in[3];
    const float* ad1 = (const float*)d_in[4];
    const float* b1  = (const float*)d_in[5];
    const float* W2  = (const float*)d_in[6];
    const float* as2 = (const float*)d_in[7];
    const float* ad2 = (const float*)d_in[8];
    const float* b2  = (const float*)d_in[9];
    float* out = (float*)d_out;

    int nE = in_sizes[1] / 2;                 // 1,700,000
    const int* src = ei;
    const int* dst = ei + nE;

    const int T = 256;
    k_init <<<(NN * H1DIM + T - 1) / T, T>>>(out, b1, b2);
    k_gemm1<<<(NN + 3) / 4, 256>>>(x, W1, as1, ad1);
    k_edge1<<<(nE * HEADS + T - 1) / T, T>>>(src, dst, nE);
    k_scat1<<<(nE * HEADS + T - 1) / T, T>>>(src, dst, nE);
    k_elu  <<<(NN * H1DIM + T - 1) / T, T>>>();
    k_gemm2<<<(NN + 7) / 8, 320>>>(W2);
    k_att2 <<<(NN + T - 1) / T, T>>>(as2, ad2);
    k_edge2<<<(nE + T - 1) / T, T>>>(src, dst, nE);
    {
        long total = (long)nE * OUTC;
        k_scat2<<<(int)((total + T - 1) / T), T>>>(src, dst, nE, out);
    }
}

// round 3
// speedup vs baseline: 6.1744x; 6.1744x over previous
#include <cuda_runtime.h>

#define NN    100000
#define EMAX  1700000
#define INC   128
#define H1DIM 64
#define HEADS 8
#define HID   8
#define OUTC  40
#define FULL  0xffffffffu

// ---- scratch ----
__device__ float g_h1[NN * H1DIM];
__device__ float g_as1[NN * HEADS];
__device__ float g_ad1[NN * HEADS];
__device__ float g_act1[NN * H1DIM];
__device__ float g_h2[NN * OUTC];
__device__ float g_as2[NN];
__device__ float g_ad2[NN];
__device__ int   g_cnt[NN];
__device__ int   g_cur[NN];
__device__ int   g_rowptr[NN + 1];
__device__ int   g_blocksum[1024];
__device__ int   g_csr_src[EMAX];

// ---- zero the CSR counters ----
__global__ void __launch_bounds__(256) k_init() {
    int i = blockIdx.x * blockDim.x + threadIdx.x;
    if (i < NN) { g_cnt[i] = 0; g_cur[i] = 0; }
}

// ---- histogram of destinations ----
__global__ void __launch_bounds__(256) k_hist(const int* __restrict__ dst, int nE) {
    int e = blockIdx.x * blockDim.x + threadIdx.x;
    if (e < nE) atomicAdd(&g_cnt[dst[e]], 1);
}

// ---- scan phase A: per-chunk sums (1024 chunks of 98) ----
__global__ void __launch_bounds__(1024) k_scanA() {
    const int t = threadIdx.x;
    const int CH = (NN + 1023) / 1024;   // 98
    int base = t * CH;
    int sum = 0;
    for (int i = 0; i < CH; i++) {
        int idx = base + i;
        if (idx < NN) sum += g_cnt[idx];
    }
    g_blocksum[t] = sum;
}

// ---- scan phase B: scan chunk sums, write rowptr ----
__global__ void __launch_bounds__(1024) k_scanB() {
    __shared__ int sm[1024];
    const int t = threadIdx.x;
    const int CH = (NN + 1023) / 1024;
    int mysum = g_blocksum[t];
    sm[t] = mysum;
    __syncthreads();
    for (int d = 1; d < 1024; d <<= 1) {
        int v = (t >= d) ? sm[t - d] : 0;
        __syncthreads();
        sm[t] += v;
        __syncthreads();
    }
    int run = sm[t] - mysum;             // exclusive prefix for this chunk
    int base = t * CH;
    for (int i = 0; i < CH; i++) {
        int idx = base + i;
        if (idx < NN) { g_rowptr[idx] = run; run += g_cnt[idx]; }
    }
    if (t == 1023) g_rowptr[NN] = sm[1023];
}

// ---- CSR fill ----
__global__ void __launch_bounds__(256) k_fill(const int* __restrict__ src,
                                              const int* __restrict__ dst, int nE) {
    int e = blockIdx.x * blockDim.x + threadIdx.x;
    if (e >= nE) return;
    int d = dst[e];
    int p = g_rowptr[d] + atomicAdd(&g_cur[d], 1);
    g_csr_src[p] = src[e];
}

// ---- layer-1 GEMM + attention dots: 16 nodes/block, 256 threads ----
__global__ void __launch_bounds__(256) k_gemm1(
        const float* __restrict__ x,  const float* __restrict__ W1,
        const float* __restrict__ as_w, const float* __restrict__ ad_w) {
    __shared__ float wT[INC * H1DIM];     // wT[k*64+f] = W1[f*128+k]   (32KB)
    __shared__ float xs[16 * INC];        // 8KB
    const int t = threadIdx.x;
    const int nb = blockIdx.x * 16;

    for (int i = t; i < H1DIM * INC; i += 256) {
        int f = i >> 7, k = i & 127;
        wT[k * H1DIM + f] = W1[i];
    }
    for (int i = t; i < 16 * INC; i += 256) {
        int node = nb + (i >> 7);
        xs[i] = x[node * INC + (i & 127)];
    }
    __syncthreads();

    const int f = t & 63;
    const int g = t >> 6;
    float acc[4] = {0.f, 0.f, 0.f, 0.f};

    const float4* xr0 = (const float4*)(xs + (g +  0) * INC);
    const float4* xr1 = (const float4*)(xs + (g +  4) * INC);
    const float4* xr2 = (const float4*)(xs + (g +  8) * INC);
    const float4* xr3 = (const float4*)(xs + (g + 12) * INC);

    #pragma unroll 4
    for (int k4 = 0; k4 < INC / 4; k4++) {
        int kb = k4 * 4;
        float w0 = wT[(kb + 0) * H1DIM + f];
        float w1 = wT[(kb + 1) * H1DIM + f];
        float w2 = wT[(kb + 2) * H1DIM + f];
        float w3 = wT[(kb + 3) * H1DIM + f];
        float4 v;
        v = xr0[k4]; acc[0] += v.x*w0 + v.y*w1 + v.z*w2 + v.w*w3;
        v = xr1[k4]; acc[1] += v.x*w0 + v.y*w1 + v.z*w2 + v.w*w3;
        v = xr2[k4]; acc[2] += v.x*w0 + v.y*w1 + v.z*w2 + v.w*w3;
        v = xr3[k4]; acc[3] += v.x*w0 + v.y*w1 + v.z*w2 + v.w*w3;
    }

    float aw = as_w[f], dw = ad_w[f];
    #pragma unroll
    for (int i = 0; i < 4; i++) {
        int node = nb + g + 4 * i;
        float vs = acc[i] * aw, vd = acc[i] * dw;
        #pragma unroll
        for (int off = 1; off < HID; off <<= 1) {
            vs += __shfl_xor_sync(FULL, vs, off);
            vd += __shfl_xor_sync(FULL, vd, off);
        }
        g_h1[node * H1DIM + f] = acc[i];
        if ((f & 7) == 0) {
            g_as1[node * HEADS + (f >> 3)] = vs;
            g_ad1[node * HEADS + (f >> 3)] = vd;
        }
    }
}

// ---- layer-1 aggregation: warp per dst node, atomic-free ----
__global__ void __launch_bounds__(256) k_agg1(const float* __restrict__ b1) {
    int n = blockIdx.x * 8 + (threadIdx.x >> 5);
    int l = threadIdx.x & 31;
    int start = g_rowptr[n], end = g_rowptr[n + 1];

    const int g  = l >> 3;                // edge-slot within chunk of 4
    const int h  = l & 7;                 // head for the ex computation
    const int hA = l >> 3;                // head of channel c0 = l
    const int hB = hA + 4;                // head of channel c1 = l + 32
    float adh = g_ad1[n * HEADS + h];

    float acc0 = 0.f, acc1 = 0.f, den = 0.f;
    for (int eb = start; eb < end; eb += 4) {
        int m = end - eb; if (m > 4) m = 4;
        int s = 0; float ex = 0.f;
        if (g < m) {
            s = g_csr_src[eb + g];
            float v = g_as1[s * HEADS + h] + adh;
            v = (v > 0.f) ? v : 0.2f * v;
            ex = __expf(v);
        }
        den += ex;
        #pragma unroll
        for (int j = 0; j < 4; j++) {
            if (j >= m) break;
            int   sj  = __shfl_sync(FULL, s,  j * 8);
            float exA = __shfl_sync(FULL, ex, j * 8 + hA);
            float exB = __shfl_sync(FULL, ex, j * 8 + hB);
            acc0 += exA * g_h1[sj * H1DIM + l];
            acc1 += exB * g_h1[sj * H1DIM + 32 + l];
        }
    }
    den += __shfl_xor_sync(FULL, den, 8);
    den += __shfl_xor_sync(FULL, den, 16);   // lane l now has denom[l&7]
    float dA = __shfl_sync(FULL, den, hA);
    float dB = __shfl_sync(FULL, den, hB);

    float o0 = acc0 / dA + b1[l];
    float o1 = acc1 / dB + b1[32 + l];
    g_act1[n * H1DIM + l]      = (o0 > 0.f) ? o0 : expm1f(o0);
    g_act1[n * H1DIM + 32 + l] = (o1 > 0.f) ? o1 : expm1f(o1);
}

// ---- layer-2 GEMM: 8 nodes/block, 320 threads ----
__global__ void __launch_bounds__(320) k_gemm2(const float* __restrict__ W2) {
    __shared__ float wT[H1DIM * OUTC];    // wT[k*40+f] = W2[f*64+k]  (10KB)
    __shared__ float a[8 * H1DIM];        // 2KB
    const int t = threadIdx.x;
    const int nb = blockIdx.x * 8;

    for (int i = t; i < OUTC * H1DIM; i += 320) {
        int f = i >> 6, k = i & 63;
        wT[k * OUTC + f] = W2[i];
    }
    for (int i = t; i < 8 * H1DIM; i += 320) {
        int node = nb + (i >> 6);
        a[i] = g_act1[node * H1DIM + (i & 63)];
    }
    __syncthreads();

    const int f = t % OUTC;
    const int local = t / OUTC;
    const float4* ar = (const float4*)(a + local * H1DIM);
    float acc = 0.f;
    #pragma unroll 4
    for (int k4 = 0; k4 < H1DIM / 4; k4++) {
        int kb = k4 * 4;
        float4 v = ar[k4];
        acc += v.x * wT[(kb + 0) * OUTC + f];
        acc += v.y * wT[(kb + 1) * OUTC + f];
        acc += v.z * wT[(kb + 2) * OUTC + f];
        acc += v.w * wT[(kb + 3) * OUTC + f];
    }
    g_h2[(nb + local) * OUTC + f] = acc;
}

// ---- layer-2 attention dots ----
__global__ void __launch_bounds__(256) k_att2(const float* __restrict__ as_w,
                                              const float* __restrict__ ad_w) {
    int n = blockIdx.x * blockDim.x + threadIdx.x;
    if (n >= NN) return;
    const float* hp = g_h2 + n * OUTC;
    float s = 0.f, d = 0.f;
    #pragma unroll
    for (int i = 0; i < OUTC; i++) { float v = hp[i]; s += v * as_w[i]; d += v * ad_w[i]; }
    g_as2[n] = s;
    g_ad2[n] = d;
}

// ---- layer-2 aggregation: warp per dst node, writes final output ----
__global__ void __launch_bounds__(256) k_agg2(const float* __restrict__ b2,
                                              float* __restrict__ out) {
    int n = blockIdx.x * 8 + (threadIdx.x >> 5);
    int l = threadIdx.x & 31;
    int start = g_rowptr[n], end = g_rowptr[n + 1];
    float ad = g_ad2[n];

    float acc0 = 0.f, acc1 = 0.f, den = 0.f;
    for (int eb = start; eb < end; eb += 32) {
        int m = end - eb; if (m > 32) m = 32;
        int s = 0; float ex = 0.f;
        if (l < m) {
            s = g_csr_src[eb + l];
            float v = g_as2[s] + ad;
            v = (v > 0.f) ? v : 0.2f * v;
            ex = __expf(v);
        }
        den += ex;
        for (int j = 0; j < m; j++) {
            int   sj  = __shfl_sync(FULL, s,  j);
            float exj = __shfl_sync(FULL, ex, j);
            acc0 += exj * g_h2[sj * OUTC + l];
            if (l < 8) acc1 += exj * g_h2[sj * OUTC + 32 + l];
        }
    }
    #pragma unroll
    for (int off = 1; off < 32; off <<= 1) den += __shfl_xor_sync(FULL, den, off);

    out[n * OUTC + l] = acc0 / den + b2[l];
    if (l < 8) out[n * OUTC + 32 + l] = acc1 / den + b2[32 + l];
}

extern "C" void kernel_launch(void* const* d_in, const int* in_sizes, int n_in,
                              void* d_out, int out_size) {
    const float* x   = (const float*)d_in[0];
    const int*   ei  = (const int*)  d_in[1];
    const float* W1  = (const float*)d_in[2];
    const float* as1 = (const float*)d_in[3];
    const float* ad1 = (const float*)d_in[4];
    const float* b1  = (const float*)d_in[5];
    const float* W2  = (const float*)d_in[6];
    const float* as2 = (const float*)d_in[7];
    const float* ad2 = (const float*)d_in[8];
    const float* b2  = (const float*)d_in[9];
    float* out = (float*)d_out;

    int nE = in_sizes[1] / 2;
    const int* src = ei;
    const int* dst = ei + nE;

    const int T = 256;
    int eg = (nE + T - 1) / T;

    k_init <<<(NN + T - 1) / T, T>>>();
    k_hist <<<eg, T>>>(dst, nE);
    k_scanA<<<1, 1024>>>();
    k_scanB<<<1, 1024>>>();
    k_fill <<<eg, T>>>(src, dst, nE);

    k_gemm1<<<NN / 16, 256>>>(x, W1, as1, ad1);
    k_agg1 <<<NN / 8, 256>>>(b1);

    k_gemm2<<<NN / 8, 320>>>(W2);
    k_att2 <<<(NN + T - 1) / T, T>>>(as2, ad2);
    k_agg2 <<<NN / 8, 256>>>(b2, out);
}

// round 4
// speedup vs baseline: 7.0178x; 1.1366x over previous
#include <cuda_runtime.h>

#define NN    100000
#define EMAX  1700000
#define INC   128
#define H1DIM 64
#define HEADS 8
#define HID   8
#define OUTC  40
#define FULL  0xffffffffu
#define SCANB 98            // ceil(NN/1024)

// ---- scratch ----
__device__ float g_h1[NN * H1DIM];
__device__ float g_as1[NN * HEADS];
__device__ float g_ad1[NN * HEADS];
__device__ float g_act1[NN * H1DIM];
__device__ float g_h2[NN * OUTC];
__device__ float g_as2[NN];
__device__ float g_ad2[NN];
__device__ int   g_cnt[NN];
__device__ int   g_cur[NN];
__device__ int   g_rowptr[NN + 1];
__device__ int   g_blocksum[SCANB];
__device__ int   g_blockoff[SCANB];
__device__ int   g_csr_src[EMAX];

// ---- zero the CSR counters ----
__global__ void __launch_bounds__(256) k_init() {
    int i = blockIdx.x * blockDim.x + threadIdx.x;
    if (i < NN) { g_cnt[i] = 0; g_cur[i] = 0; }
}

// ---- histogram of destinations ----
__global__ void __launch_bounds__(256) k_hist(const int* __restrict__ dst, int nE) {
    int e = blockIdx.x * blockDim.x + threadIdx.x;
    if (e < nE) atomicAdd(&g_cnt[dst[e]], 1);
}

// ---- scan phase A: per-block sums (98 blocks x 1024, coalesced) ----
__global__ void __launch_bounds__(1024) k_scanA() {
    __shared__ int sm[1024];
    int t = threadIdx.x;
    int i = blockIdx.x * 1024 + t;
    sm[t] = (i < NN) ? g_cnt[i] : 0;
    __syncthreads();
    for (int d = 512; d > 0; d >>= 1) {
        if (t < d) sm[t] += sm[t + d];
        __syncthreads();
    }
    if (t == 0) g_blocksum[blockIdx.x] = sm[0];
}

// ---- scan phase B: exclusive scan of 98 block sums (tiny) ----
__global__ void __launch_bounds__(128) k_scanB() {
    __shared__ int sm[128];
    int t = threadIdx.x;
    int v = (t < SCANB) ? g_blocksum[t] : 0;
    sm[t] = v;
    __syncthreads();
    for (int d = 1; d < 128; d <<= 1) {
        int u = (t >= d) ? sm[t - d] : 0;
        __syncthreads();
        sm[t] += u;
        __syncthreads();
    }
    if (t < SCANB) g_blockoff[t] = sm[t] - v;   // exclusive
    if (t == SCANB - 1) g_rowptr[NN] = sm[t];   // total edges
}

// ---- scan phase C: in-block scan, write rowptr (exclusive) ----
__global__ void __launch_bounds__(1024) k_scanC() {
    __shared__ int sm[1024];
    int t = threadIdx.x;
    int i = blockIdx.x * 1024 + t;
    int v = (i < NN) ? g_cnt[i] : 0;
    sm[t] = v;
    __syncthreads();
    for (int d = 1; d < 1024; d <<= 1) {
        int u = (t >= d) ? sm[t - d] : 0;
        __syncthreads();
        sm[t] += u;
        __syncthreads();
    }
    if (i < NN) g_rowptr[i] = g_blockoff[blockIdx.x] + sm[t] - v;
}

// ---- CSR fill ----
__global__ void __launch_bounds__(256) k_fill(const int* __restrict__ src,
                                              const int* __restrict__ dst, int nE) {
    int e = blockIdx.x * blockDim.x + threadIdx.x;
    if (e >= nE) return;
    int d = dst[e];
    int p = g_rowptr[d] + atomicAdd(&g_cur[d], 1);
    g_csr_src[p] = src[e];
}

// ---- layer-1 GEMM + attention dots: 16 nodes/block, 256 threads ----
__global__ void __launch_bounds__(256) k_gemm1(
        const float* __restrict__ x,  const float* __restrict__ W1,
        const float* __restrict__ as_w, const float* __restrict__ ad_w) {
    __shared__ float wT[INC * H1DIM];     // 32KB
    __shared__ float xs[16 * INC];        // 8KB
    const int t = threadIdx.x;
    const int nb = blockIdx.x * 16;

    for (int i = t; i < H1DIM * INC; i += 256) {
        int f = i >> 7, k = i & 127;
        wT[k * H1DIM + f] = W1[i];
    }
    for (int i = t; i < 16 * INC; i += 256) {
        int node = nb + (i >> 7);
        xs[i] = x[node * INC + (i & 127)];
    }
    __syncthreads();

    const int f = t & 63;
    const int g = t >> 6;
    float acc[4] = {0.f, 0.f, 0.f, 0.f};

    const float4* xr0 = (const float4*)(xs + (g +  0) * INC);
    const float4* xr1 = (const float4*)(xs + (g +  4) * INC);
    const float4* xr2 = (const float4*)(xs + (g +  8) * INC);
    const float4* xr3 = (const float4*)(xs + (g + 12) * INC);

    #pragma unroll 4
    for (int k4 = 0; k4 < INC / 4; k4++) {
        int kb = k4 * 4;
        float w0 = wT[(kb + 0) * H1DIM + f];
        float w1 = wT[(kb + 1) * H1DIM + f];
        float w2 = wT[(kb + 2) * H1DIM + f];
        float w3 = wT[(kb + 3) * H1DIM + f];
        float4 v;
        v = xr0[k4]; acc[0] += v.x*w0 + v.y*w1 + v.z*w2 + v.w*w3;
        v = xr1[k4]; acc[1] += v.x*w0 + v.y*w1 + v.z*w2 + v.w*w3;
        v = xr2[k4]; acc[2] += v.x*w0 + v.y*w1 + v.z*w2 + v.w*w3;
        v = xr3[k4]; acc[3] += v.x*w0 + v.y*w1 + v.z*w2 + v.w*w3;
    }

    float aw = as_w[f], dw = ad_w[f];
    #pragma unroll
    for (int i = 0; i < 4; i++) {
        int node = nb + g + 4 * i;
        float vs = acc[i] * aw, vd = acc[i] * dw;
        #pragma unroll
        for (int off = 1; off < HID; off <<= 1) {
            vs += __shfl_xor_sync(FULL, vs, off);
            vd += __shfl_xor_sync(FULL, vd, off);
        }
        g_h1[node * H1DIM + f] = acc[i];
        if ((f & 7) == 0) {
            g_as1[node * HEADS + (f >> 3)] = vs;
            g_ad1[node * HEADS + (f >> 3)] = vd;
        }
    }
}

// ---- layer-1 aggregation: warp per dst node, atomic-free ----
__global__ void __launch_bounds__(256) k_agg1(const float* __restrict__ b1) {
    int n = blockIdx.x * 8 + (threadIdx.x >> 5);
    int l = threadIdx.x & 31;
    int start = g_rowptr[n], end = g_rowptr[n + 1];

    const int g  = l >> 3;
    const int h  = l & 7;
    const int hA = l >> 3;
    const int hB = hA + 4;
    float adh = g_ad1[n * HEADS + h];

    float acc0 = 0.f, acc1 = 0.f, den = 0.f;
    for (int eb = start; eb < end; eb += 4) {
        int m = end - eb; if (m > 4) m = 4;
        int s = 0; float ex = 0.f;
        if (g < m) {
            s = g_csr_src[eb + g];
            float v = g_as1[s * HEADS + h] + adh;
            v = (v > 0.f) ? v : 0.2f * v;
            ex = __expf(v);
        }
        den += ex;
        #pragma unroll
        for (int j = 0; j < 4; j++) {
            if (j >= m) break;
            int   sj  = __shfl_sync(FULL, s,  j * 8);
            float exA = __shfl_sync(FULL, ex, j * 8 + hA);
            float exB = __shfl_sync(FULL, ex, j * 8 + hB);
            acc0 += exA * g_h1[sj * H1DIM + l];
            acc1 += exB * g_h1[sj * H1DIM + 32 + l];
        }
    }
    den += __shfl_xor_sync(FULL, den, 8);
    den += __shfl_xor_sync(FULL, den, 16);
    float dA = __shfl_sync(FULL, den, hA);
    float dB = __shfl_sync(FULL, den, hB);

    float o0 = acc0 / dA + b1[l];
    float o1 = acc1 / dB + b1[32 + l];
    g_act1[n * H1DIM + l]      = (o0 > 0.f) ? o0 : expm1f(o0);
    g_act1[n * H1DIM + 32 + l] = (o1 > 0.f) ? o1 : expm1f(o1);
}

// ---- layer-2 GEMM + fused attention dots: 8 nodes/block, 320 threads ----
__global__ void __launch_bounds__(320) k_gemm2(const float* __restrict__ W2,
                                               const float* __restrict__ as_w,
                                               const float* __restrict__ ad_w) {
    __shared__ float wT[H1DIM * OUTC];    // 10KB
    __shared__ float a[8 * H1DIM];        // 2KB
    __shared__ float ps[8 * OUTC];        // src products
    __shared__ float pd[8 * OUTC];        // dst products
    const int t = threadIdx.x;
    const int nb = blockIdx.x * 8;

    for (int i = t; i < OUTC * H1DIM; i += 320) {
        int f = i >> 6, k = i & 63;
        wT[k * OUTC + f] = W2[i];
    }
    for (int i = t; i < 8 * H1DIM; i += 320) {
        int node = nb + (i >> 6);
        a[i] = g_act1[node * H1DIM + (i & 63)];
    }
    __syncthreads();

    const int f = t % OUTC;
    const int local = t / OUTC;
    const float4* ar = (const float4*)(a + local * H1DIM);
    float acc = 0.f;
    #pragma unroll 4
    for (int k4 = 0; k4 < H1DIM / 4; k4++) {
        int kb = k4 * 4;
        float4 v = ar[k4];
        acc += v.x * wT[(kb + 0) * OUTC + f];
        acc += v.y * wT[(kb + 1) * OUTC + f];
        acc += v.z * wT[(kb + 2) * OUTC + f];
        acc += v.w * wT[(kb + 3) * OUTC + f];
    }
    g_h2[(nb + local) * OUTC + f] = acc;
    ps[local * OUTC + f] = acc * as_w[f];
    pd[local * OUTC + f] = acc * ad_w[f];
    __syncthreads();

    // 8 threads fold 40 products each for src & dst dots
    if (t < 16) {
        int node = t & 7;
        const float* p = (t < 8) ? (ps + node * OUTC) : (pd + node * OUTC);
        float s = 0.f;
        #pragma unroll
        for (int i = 0; i < OUTC; i++) s += p[i];
        if (t < 8) g_as2[nb + node] = s;
        else       g_ad2[nb + node] = s;
    }
}

// ---- layer-2 aggregation: warp per dst node, writes final output ----
__global__ void __launch_bounds__(256) k_agg2(const float* __restrict__ b2,
                                              float* __restrict__ out) {
    int n = blockIdx.x * 8 + (threadIdx.x >> 5);
    int l = threadIdx.x & 31;
    int start = g_rowptr[n], end = g_rowptr[n + 1];
    float ad = g_ad2[n];

    float acc0 = 0.f, acc1 = 0.f, den = 0.f;
    for (int eb = start; eb < end; eb += 32) {
        int m = end - eb; if (m > 32) m = 32;
        int s = 0; float ex = 0.f;
        if (l < m) {
            s = g_csr_src[eb + l];
            float v = g_as2[s] + ad;
            v = (v > 0.f) ? v : 0.2f * v;
            ex = __expf(v);
        }
        den += ex;
        for (int j = 0; j < m; j++) {
            int   sj  = __shfl_sync(FULL, s,  j);
            float exj = __shfl_sync(FULL, ex, j);
            acc0 += exj * g_h2[sj * OUTC + l];
            if (l < 8) acc1 += exj * g_h2[sj * OUTC + 32 + l];
        }
    }
    #pragma unroll
    for (int off = 1; off < 32; off <<= 1) den += __shfl_xor_sync(FULL, den, off);

    out[n * OUTC + l] = acc0 / den + b2[l];
    if (l < 8) out[n * OUTC + 32 + l] = acc1 / den + b2[32 + l];
}

extern "C" void kernel_launch(void* const* d_in, const int* in_sizes, int n_in,
                              void* d_out, int out_size) {
    const float* x   = (const float*)d_in[0];
    const int*   ei  = (const int*)  d_in[1];
    const float* W1  = (const float*)d_in[2];
    const float* as1 = (const float*)d_in[3];
    const float* ad1 = (const float*)d_in[4];
    const float* b1  = (const float*)d_in[5];
    const float* W2  = (const float*)d_in[6];
    const float* as2 = (const float*)d_in[7];
    const float* ad2 = (const float*)d_in[8];
    const float* b2  = (const float*)d_in[9];
    float* out = (float*)d_out;

    int nE = in_sizes[1] / 2;
    const int* src = ei;
    const int* dst = ei + nE;

    const int T = 256;
    int eg = (nE + T - 1) / T;

    k_init <<<(NN + T - 1) / T, T>>>();
    k_hist <<<eg, T>>>(dst, nE);
    k_scanA<<<SCANB, 1024>>>();
    k_scanB<<<1, 128>>>();
    k_scanC<<<SCANB, 1024>>>();
    k_fill <<<eg, T>>>(src, dst, nE);

    k_gemm1<<<NN / 16, 256>>>(x, W1, as1, ad1);
    k_agg1 <<<NN / 8, 256>>>(b1);

    k_gemm2<<<NN / 8, 320>>>(W2, as2, ad2);
    k_agg2 <<<NN / 8, 256>>>(b2, out);
}

// round 5
// speedup vs baseline: 7.5075x; 1.0698x over previous
#include <cuda_runtime.h>

#define NN    100000
#define EMAX  1700000
#define INC   128
#define H1DIM 64
#define HEADS 8
#define HID   8
#define OUTC  40
#define FULL  0xffffffffu
#define SCANB 98            // ceil(NN/1024)

// ---- scratch ----
__device__ float g_h1[NN * H1DIM];
__device__ float g_as1[NN * HEADS];
__device__ float g_ad1[NN * HEADS];
__device__ float g_act1[NN * H1DIM];
__device__ float g_h2[NN * OUTC];
__device__ float g_as2[NN];
__device__ float g_ad2[NN];
__device__ int   g_cnt[NN];
__device__ int   g_cur[NN];
__device__ int   g_rowptr[NN + 1];
__device__ int   g_blocksum[SCANB];
__device__ int   g_blockoff[SCANB];
__device__ int   g_csr_src[EMAX];

// ---- zero the CSR counters ----
__global__ void __launch_bounds__(256) k_init() {
    int i = blockIdx.x * blockDim.x + threadIdx.x;
    if (i < NN) { g_cnt[i] = 0; g_cur[i] = 0; }
}

// ---- histogram of destinations ----
__global__ void __launch_bounds__(256) k_hist(const int* __restrict__ dst, int nE) {
    int e = blockIdx.x * blockDim.x + threadIdx.x;
    if (e < nE) atomicAdd(&g_cnt[dst[e]], 1);
}

// ---- scan phase A: per-block sums ----
__global__ void __launch_bounds__(1024) k_scanA() {
    __shared__ int sm[1024];
    int t = threadIdx.x;
    int i = blockIdx.x * 1024 + t;
    sm[t] = (i < NN) ? g_cnt[i] : 0;
    __syncthreads();
    for (int d = 512; d > 0; d >>= 1) {
        if (t < d) sm[t] += sm[t + d];
        __syncthreads();
    }
    if (t == 0) g_blocksum[blockIdx.x] = sm[0];
}

// ---- scan phase B: exclusive scan of block sums ----
__global__ void __launch_bounds__(128) k_scanB() {
    __shared__ int sm[128];
    int t = threadIdx.x;
    int v = (t < SCANB) ? g_blocksum[t] : 0;
    sm[t] = v;
    __syncthreads();
    for (int d = 1; d < 128; d <<= 1) {
        int u = (t >= d) ? sm[t - d] : 0;
        __syncthreads();
        sm[t] += u;
        __syncthreads();
    }
    if (t < SCANB) g_blockoff[t] = sm[t] - v;
    if (t == SCANB - 1) g_rowptr[NN] = sm[t];
}

// ---- scan phase C: in-block scan, write rowptr ----
__global__ void __launch_bounds__(1024) k_scanC() {
    __shared__ int sm[1024];
    int t = threadIdx.x;
    int i = blockIdx.x * 1024 + t;
    int v = (i < NN) ? g_cnt[i] : 0;
    sm[t] = v;
    __syncthreads();
    for (int d = 1; d < 1024; d <<= 1) {
        int u = (t >= d) ? sm[t - d] : 0;
        __syncthreads();
        sm[t] += u;
        __syncthreads();
    }
    if (i < NN) g_rowptr[i] = g_blockoff[blockIdx.x] + sm[t] - v;
}

// ---- CSR fill ----
__global__ void __launch_bounds__(256) k_fill(const int* __restrict__ src,
                                              const int* __restrict__ dst, int nE) {
    int e = blockIdx.x * blockDim.x + threadIdx.x;
    if (e >= nE) return;
    int d = dst[e];
    int p = g_rowptr[d] + atomicAdd(&g_cur[d], 1);
    g_csr_src[p] = src[e];
}

// ---- layer-1 GEMM + attention dots ----
__global__ void __launch_bounds__(256) k_gemm1(
        const float* __restrict__ x,  const float* __restrict__ W1,
        const float* __restrict__ as_w, const float* __restrict__ ad_w) {
    __shared__ float wT[INC * H1DIM];
    __shared__ float xs[16 * INC];
    const int t = threadIdx.x;
    const int nb = blockIdx.x * 16;

    for (int i = t; i < H1DIM * INC; i += 256) {
        int f = i >> 7, k = i & 127;
        wT[k * H1DIM + f] = W1[i];
    }
    for (int i = t; i < 16 * INC; i += 256) {
        int node = nb + (i >> 7);
        xs[i] = x[node * INC + (i & 127)];
    }
    __syncthreads();

    const int f = t & 63;
    const int g = t >> 6;
    float acc[4] = {0.f, 0.f, 0.f, 0.f};

    const float4* xr0 = (const float4*)(xs + (g +  0) * INC);
    const float4* xr1 = (const float4*)(xs + (g +  4) * INC);
    const float4* xr2 = (const float4*)(xs + (g +  8) * INC);
    const float4* xr3 = (const float4*)(xs + (g + 12) * INC);

    #pragma unroll 4
    for (int k4 = 0; k4 < INC / 4; k4++) {
        int kb = k4 * 4;
        float w0 = wT[(kb + 0) * H1DIM + f];
        float w1 = wT[(kb + 1) * H1DIM + f];
        float w2 = wT[(kb + 2) * H1DIM + f];
        float w3 = wT[(kb + 3) * H1DIM + f];
        float4 v;
        v = xr0[k4]; acc[0] += v.x*w0 + v.y*w1 + v.z*w2 + v.w*w3;
        v = xr1[k4]; acc[1] += v.x*w0 + v.y*w1 + v.z*w2 + v.w*w3;
        v = xr2[k4]; acc[2] += v.x*w0 + v.y*w1 + v.z*w2 + v.w*w3;
        v = xr3[k4]; acc[3] += v.x*w0 + v.y*w1 + v.z*w2 + v.w*w3;
    }

    float aw = as_w[f], dw = ad_w[f];
    #pragma unroll
    for (int i = 0; i < 4; i++) {
        int node = nb + g + 4 * i;
        float vs = acc[i] * aw, vd = acc[i] * dw;
        #pragma unroll
        for (int off = 1; off < HID; off <<= 1) {
            vs += __shfl_xor_sync(FULL, vs, off);
            vd += __shfl_xor_sync(FULL, vd, off);
        }
        g_h1[node * H1DIM + f] = acc[i];
        if ((f & 7) == 0) {
            g_as1[node * HEADS + (f >> 3)] = vs;
            g_ad1[node * HEADS + (f >> 3)] = vd;
        }
    }
}

// ---- layer-1 aggregation: warp per dst node, prefetched pipeline ----
__global__ void __launch_bounds__(256) k_agg1(const float* __restrict__ b1) {
    int n = blockIdx.x * 8 + (threadIdx.x >> 5);
    int l = threadIdx.x & 31;
    int start = g_rowptr[n], end = g_rowptr[n + 1];

    const int g  = l >> 3;
    const int h  = l & 7;
    const int hA = l >> 3;
    const int hB = hA + 4;
    float adh = g_ad1[n * HEADS + h];

    // prefetch first chunk
    int m = end - start; if (m > 4) m = 4;
    int s = 0; float v = 0.f;
    if (g < m) {
        s = g_csr_src[start + g];
        v = g_as1[s * HEADS + h] + adh;
    }

    float acc0 = 0.f, acc1 = 0.f, den = 0.f;
    for (int eb = start; eb < end; eb += 4) {
        // prefetch next chunk (hides csr+as1 latency behind current h1 work)
        int ebn = eb + 4;
        int mn = end - ebn; if (mn > 4) mn = 4;
        int sn = 0; float vn = 0.f;
        if (g < mn) {
            sn = g_csr_src[ebn + g];
            vn = g_as1[sn * HEADS + h] + adh;
        }

        float lv = (v > 0.f) ? v : 0.2f * v;
        float ex = (g < m) ? __expf(lv) : 0.f;
        den += ex;
        #pragma unroll
        for (int j = 0; j < 4; j++) {
            if (j >= m) break;
            int   sj  = __shfl_sync(FULL, s,  j * 8);
            float exA = __shfl_sync(FULL, ex, j * 8 + hA);
            float exB = __shfl_sync(FULL, ex, j * 8 + hB);
            acc0 += exA * g_h1[sj * H1DIM + l];
            acc1 += exB * g_h1[sj * H1DIM + 32 + l];
        }
        m = mn; s = sn; v = vn;
    }
    den += __shfl_xor_sync(FULL, den, 8);
    den += __shfl_xor_sync(FULL, den, 16);
    float dA = __shfl_sync(FULL, den, hA);
    float dB = __shfl_sync(FULL, den, hB);

    float o0 = acc0 / dA + b1[l];
    float o1 = acc1 / dB + b1[32 + l];
    g_act1[n * H1DIM + l]      = (o0 > 0.f) ? o0 : expm1f(o0);
    g_act1[n * H1DIM + 32 + l] = (o1 > 0.f) ? o1 : expm1f(o1);
}

// ---- layer-2 GEMM + fused attention dots ----
__global__ void __launch_bounds__(320) k_gemm2(const float* __restrict__ W2,
                                               const float* __restrict__ as_w,
                                               const float* __restrict__ ad_w) {
    __shared__ float wT[H1DIM * OUTC];
    __shared__ float a[8 * H1DIM];
    __shared__ float ps[8 * OUTC];
    __shared__ float pd[8 * OUTC];
    const int t = threadIdx.x;
    const int nb = blockIdx.x * 8;

    for (int i = t; i < OUTC * H1DIM; i += 320) {
        int f = i >> 6, k = i & 63;
        wT[k * OUTC + f] = W2[i];
    }
    for (int i = t; i < 8 * H1DIM; i += 320) {
        int node = nb + (i >> 6);
        a[i] = g_act1[node * H1DIM + (i & 63)];
    }
    __syncthreads();

    const int f = t % OUTC;
    const int local = t / OUTC;
    const float4* ar = (const float4*)(a + local * H1DIM);
    float acc = 0.f;
    #pragma unroll 4
    for (int k4 = 0; k4 < H1DIM / 4; k4++) {
        int kb = k4 * 4;
        float4 v = ar[k4];
        acc += v.x * wT[(kb + 0) * OUTC + f];
        acc += v.y * wT[(kb + 1) * OUTC + f];
        acc += v.z * wT[(kb + 2) * OUTC + f];
        acc += v.w * wT[(kb + 3) * OUTC + f];
    }
    g_h2[(nb + local) * OUTC + f] = acc;
    ps[local * OUTC + f] = acc * as_w[f];
    pd[local * OUTC + f] = acc * ad_w[f];
    __syncthreads();

    if (t < 16) {
        int node = t & 7;
        const float* p = (t < 8) ? (ps + node * OUTC) : (pd + node * OUTC);
        float s = 0.f;
        #pragma unroll
        for (int i = 0; i < OUTC; i++) s += p[i];
        if (t < 8) g_as2[nb + node] = s;
        else       g_ad2[nb + node] = s;
    }
}

// ---- layer-2 aggregation: warp per dst node, prefetched pipeline ----
__global__ void __launch_bounds__(256) k_agg2(const float* __restrict__ b2,
                                              float* __restrict__ out) {
    int n = blockIdx.x * 8 + (threadIdx.x >> 5);
    int l = threadIdx.x & 31;
    int start = g_rowptr[n], end = g_rowptr[n + 1];
    float ad = g_ad2[n];

    // prefetch first chunk
    int m = end - start; if (m > 32) m = 32;
    int s = 0; float v = 0.f;
    if (l < m) {
        s = g_csr_src[start + l];
        v = g_as2[s] + ad;
    }

    float acc0 = 0.f, acc1 = 0.f, den = 0.f;
    for (int eb = start; eb < end; eb += 32) {
        int ebn = eb + 32;
        int mn = end - ebn; if (mn > 32) mn = 32;
        int sn = 0; float vn = 0.f;
        if (l < mn) {
            sn = g_csr_src[ebn + l];
            vn = g_as2[sn] + ad;
        }

        float lv = (v > 0.f) ? v : 0.2f * v;
        float ex = (l < m) ? __expf(lv) : 0.f;
        den += ex;
        for (int j = 0; j < m; j++) {
            int   sj  = __shfl_sync(FULL, s,  j);
            float exj = __shfl_sync(FULL, ex, j);
            acc0 += exj * g_h2[sj * OUTC + l];
            if (l < 8) acc1 += exj * g_h2[sj * OUTC + 32 + l];
        }
        m = mn; s = sn; v = vn;
    }
    #pragma unroll
    for (int off = 1; off < 32; off <<= 1) den += __shfl_xor_sync(FULL, den, off);

    out[n * OUTC + l] = acc0 / den + b2[l];
    if (l < 8) out[n * OUTC + 32 + l] = acc1 / den + b2[32 + l];
}

extern "C" void kernel_launch(void* const* d_in, const int* in_sizes, int n_in,
                              void* d_out, int out_size) {
    const float* x   = (const float*)d_in[0];
    const int*   ei  = (const int*)  d_in[1];
    const float* W1  = (const float*)d_in[2];
    const float* as1 = (const float*)d_in[3];
    const float* ad1 = (const float*)d_in[4];
    const float* b1  = (const float*)d_in[5];
    const float* W2  = (const float*)d_in[6];
    const float* as2 = (const float*)d_in[7];
    const float* ad2 = (const float*)d_in[8];
    const float* b2  = (const float*)d_in[9];
    float* out = (float*)d_out;

    int nE = in_sizes[1] / 2;
    const int* src = ei;
    const int* dst = ei + nE;

    const int T = 256;
    int eg = (nE + T - 1) / T;

    // one-time side-stream + capture-safe events (DisableTiming required)
    static cudaStream_t s2 = nullptr;
    static cudaEvent_t evFork = nullptr, evJoin = nullptr;
    if (s2 == nullptr) {
        cudaStreamCreateWithFlags(&s2, cudaStreamNonBlocking);
        cudaEventCreateWithFlags(&evFork, cudaEventDisableTiming);
        cudaEventCreateWithFlags(&evJoin, cudaEventDisableTiming);
    }

    // fork: gemm1 (needs only x, W1) runs concurrently with CSR build
    cudaEventRecord(evFork, 0);
    cudaStreamWaitEvent(s2, evFork, 0);
    k_gemm1<<<NN / 16, 256, 0, s2>>>(x, W1, as1, ad1);
    cudaEventRecord(evJoin, s2);

    // main stream: CSR build
    k_init <<<(NN + T - 1) / T, T>>>();
    k_hist <<<eg, T>>>(dst, nE);
    k_scanA<<<SCANB, 1024>>>();
    k_scanB<<<1, 128>>>();
    k_scanC<<<SCANB, 1024>>>();
    k_fill <<<eg, T>>>(src, dst, nE);

    // join: agg1 needs both CSR and gemm1 results
    cudaStreamWaitEvent(0, evJoin, 0);

    k_agg1 <<<NN / 8, 256>>>(b1);
    k_gemm2<<<NN / 8, 320>>>(W2, as2, ad2);
    k_agg2 <<<NN / 8, 256>>>(b2, out);
}

// round 6
// speedup vs baseline: 8.0385x; 1.0707x over previous
#include <cuda_runtime.h>

#define NN    100000
#define EMAX  1700000
#define INC   128
#define H1DIM 64
#define HEADS 8
#define HID   8
#define OUTC  40
#define FULL  0xffffffffu
#define SCANB 98            // ceil(NN/1024)

// ---- scratch ----
__device__ float g_h1[NN * H1DIM];
__device__ float g_as1[NN * HEADS];
__device__ float g_ad1[NN * HEADS];
__device__ float g_act1[NN * H1DIM];
__device__ float g_h2[NN * OUTC];
__device__ float g_as2[NN];
__device__ float g_ad2[NN];
__device__ int   g_cnt[NN];
__device__ int   g_cur[NN];
__device__ int   g_rowptr[NN + 1];
__device__ int   g_blocksum[SCANB];
__device__ int   g_blockoff[SCANB];
__device__ int   g_csr_src[EMAX];

// ---- zero the CSR counters ----
__global__ void __launch_bounds__(256) k_init() {
    int i = blockIdx.x * blockDim.x + threadIdx.x;
    if (i < NN) { g_cnt[i] = 0; g_cur[i] = 0; }
}

// ---- histogram of destinations ----
__global__ void __launch_bounds__(256) k_hist(const int* __restrict__ dst, int nE) {
    int e = blockIdx.x * blockDim.x + threadIdx.x;
    if (e < nE) atomicAdd(&g_cnt[dst[e]], 1);
}

// ---- scan phase A ----
__global__ void __launch_bounds__(1024) k_scanA() {
    __shared__ int sm[1024];
    int t = threadIdx.x;
    int i = blockIdx.x * 1024 + t;
    sm[t] = (i < NN) ? g_cnt[i] : 0;
    __syncthreads();
    for (int d = 512; d > 0; d >>= 1) {
        if (t < d) sm[t] += sm[t + d];
        __syncthreads();
    }
    if (t == 0) g_blocksum[blockIdx.x] = sm[0];
}

// ---- scan phase B ----
__global__ void __launch_bounds__(128) k_scanB() {
    __shared__ int sm[128];
    int t = threadIdx.x;
    int v = (t < SCANB) ? g_blocksum[t] : 0;
    sm[t] = v;
    __syncthreads();
    for (int d = 1; d < 128; d <<= 1) {
        int u = (t >= d) ? sm[t - d] : 0;
        __syncthreads();
        sm[t] += u;
        __syncthreads();
    }
    if (t < SCANB) g_blockoff[t] = sm[t] - v;
    if (t == SCANB - 1) g_rowptr[NN] = sm[t];
}

// ---- scan phase C ----
__global__ void __launch_bounds__(1024) k_scanC() {
    __shared__ int sm[1024];
    int t = threadIdx.x;
    int i = blockIdx.x * 1024 + t;
    int v = (i < NN) ? g_cnt[i] : 0;
    sm[t] = v;
    __syncthreads();
    for (int d = 1; d < 1024; d <<= 1) {
        int u = (t >= d) ? sm[t - d] : 0;
        __syncthreads();
        sm[t] += u;
        __syncthreads();
    }
    if (i < NN) g_rowptr[i] = g_blockoff[blockIdx.x] + sm[t] - v;
}

// ---- CSR fill ----
__global__ void __launch_bounds__(256) k_fill(const int* __restrict__ src,
                                              const int* __restrict__ dst, int nE) {
    int e = blockIdx.x * blockDim.x + threadIdx.x;
    if (e >= nE) return;
    int d = dst[e];
    int p = g_rowptr[d] + atomicAdd(&g_cur[d], 1);
    g_csr_src[p] = src[e];
}

// ---- layer-1 GEMM + attention dots ----
__global__ void __launch_bounds__(256) k_gemm1(
        const float* __restrict__ x,  const float* __restrict__ W1,
        const float* __restrict__ as_w, const float* __restrict__ ad_w) {
    __shared__ float wT[INC * H1DIM];
    __shared__ float xs[16 * INC];
    const int t = threadIdx.x;
    const int nb = blockIdx.x * 16;

    for (int i = t; i < H1DIM * INC; i += 256) {
        int f = i >> 7, k = i & 127;
        wT[k * H1DIM + f] = W1[i];
    }
    for (int i = t; i < 16 * INC; i += 256) {
        int node = nb + (i >> 7);
        xs[i] = x[node * INC + (i & 127)];
    }
    __syncthreads();

    const int f = t & 63;
    const int g = t >> 6;
    float acc[4] = {0.f, 0.f, 0.f, 0.f};

    const float4* xr0 = (const float4*)(xs + (g +  0) * INC);
    const float4* xr1 = (const float4*)(xs + (g +  4) * INC);
    const float4* xr2 = (const float4*)(xs + (g +  8) * INC);
    const float4* xr3 = (const float4*)(xs + (g + 12) * INC);

    #pragma unroll 4
    for (int k4 = 0; k4 < INC / 4; k4++) {
        int kb = k4 * 4;
        float w0 = wT[(kb + 0) * H1DIM + f];
        float w1 = wT[(kb + 1) * H1DIM + f];
        float w2 = wT[(kb + 2) * H1DIM + f];
        float w3 = wT[(kb + 3) * H1DIM + f];
        float4 v;
        v = xr0[k4]; acc[0] += v.x*w0 + v.y*w1 + v.z*w2 + v.w*w3;
        v = xr1[k4]; acc[1] += v.x*w0 + v.y*w1 + v.z*w2 + v.w*w3;
        v = xr2[k4]; acc[2] += v.x*w0 + v.y*w1 + v.z*w2 + v.w*w3;
        v = xr3[k4]; acc[3] += v.x*w0 + v.y*w1 + v.z*w2 + v.w*w3;
    }

    float aw = as_w[f], dw = ad_w[f];
    #pragma unroll
    for (int i = 0; i < 4; i++) {
        int node = nb + g + 4 * i;
        float vs = acc[i] * aw, vd = acc[i] * dw;
        #pragma unroll
        for (int off = 1; off < HID; off <<= 1) {
            vs += __shfl_xor_sync(FULL, vs, off);
            vd += __shfl_xor_sync(FULL, vd, off);
        }
        g_h1[node * H1DIM + f] = acc[i];
        if ((f & 7) == 0) {
            g_as1[node * HEADS + (f >> 3)] = vs;
            g_ad1[node * HEADS + (f >> 3)] = vd;
        }
    }
}

// ---- layer-1 aggregation: warp/node, float2 lanes, branch-free unroll ----
// lane l owns channels (2l, 2l+1), whose head is hl = l>>2.
__global__ void __launch_bounds__(256, 6) k_agg1(const float* __restrict__ b1) {
    const int n = blockIdx.x * 8 + (threadIdx.x >> 5);
    const int l = threadIdx.x & 31;
    const int start = g_rowptr[n], end = g_rowptr[n + 1];

    const int g  = l >> 3;    // edge slot for exp phase
    const int h  = l & 7;     // head for exp phase
    const int hl = l >> 2;    // head of this lane's channel pair
    const float adh = g_ad1[n * HEADS + h];
    const float2* __restrict__ H = (const float2*)g_h1;

    // prefetch chunk 0
    int m = end - start; if (m > 4) m = 4;
    int s = 0; float v = 0.f;
    if (g < m) {
        s = g_csr_src[start + g];
        v = g_as1[s * HEADS + h] + adh;
    }

    float accx = 0.f, accy = 0.f, den = 0.f;
    for (int eb = start; eb < end; eb += 4) {
        // prefetch next chunk
        int ebn = eb + 4;
        int mn = end - ebn; if (mn > 4) mn = 4;
        int sn = 0; float vn = 0.f;
        if (g < mn) {
            sn = g_csr_src[ebn + g];
            vn = g_as1[sn * HEADS + h] + adh;
        }

        float lv = (v > 0.f) ? v : 0.2f * v;
        float ex = (g < m) ? __expf(lv) : 0.f;   // padded lanes contribute 0
        den += ex;

        int s0 = __shfl_sync(FULL, s, 0);
        int s1 = __shfl_sync(FULL, s, 8);
        int s2 = __shfl_sync(FULL, s, 16);
        int s3 = __shfl_sync(FULL, s, 24);
        float e0 = __shfl_sync(FULL, ex, hl);
        float e1 = __shfl_sync(FULL, ex, 8 + hl);
        float e2 = __shfl_sync(FULL, ex, 16 + hl);
        float e3 = __shfl_sync(FULL, ex, 24 + hl);

        float2 r0 = H[s0 * 32 + l];
        float2 r1 = H[s1 * 32 + l];
        float2 r2 = H[s2 * 32 + l];
        float2 r3 = H[s3 * 32 + l];

        accx += e0 * r0.x + e1 * r1.x + e2 * r2.x + e3 * r3.x;
        accy += e0 * r0.y + e1 * r1.y + e2 * r2.y + e3 * r3.y;

        m = mn; s = sn; v = vn;
    }
    den += __shfl_xor_sync(FULL, den, 8);
    den += __shfl_xor_sync(FULL, den, 16);       // lane l: denom of head l&7
    float dd = __shfl_sync(FULL, den, hl);

    float2 bb = ((const float2*)b1)[l];
    float o0 = accx / dd + bb.x;
    float o1 = accy / dd + bb.y;
    float2 r;
    r.x = (o0 > 0.f) ? o0 : expm1f(o0);
    r.y = (o1 > 0.f) ? o1 : expm1f(o1);
    ((float2*)g_act1)[n * 32 + l] = r;
}

// ---- layer-2 GEMM + fused attention dots ----
__global__ void __launch_bounds__(320) k_gemm2(const float* __restrict__ W2,
                                               const float* __restrict__ as_w,
                                               const float* __restrict__ ad_w) {
    __shared__ float wT[H1DIM * OUTC];
    __shared__ float a[8 * H1DIM];
    __shared__ float ps[8 * OUTC];
    __shared__ float pd[8 * OUTC];
    const int t = threadIdx.x;
    const int nb = blockIdx.x * 8;

    for (int i = t; i < OUTC * H1DIM; i += 320) {
        int f = i >> 6, k = i & 63;
        wT[k * OUTC + f] = W2[i];
    }
    for (int i = t; i < 8 * H1DIM; i += 320) {
        int node = nb + (i >> 6);
        a[i] = g_act1[node * H1DIM + (i & 63)];
    }
    __syncthreads();

    const int f = t % OUTC;
    const int local = t / OUTC;
    const float4* ar = (const float4*)(a + local * H1DIM);
    float acc = 0.f;
    #pragma unroll 4
    for (int k4 = 0; k4 < H1DIM / 4; k4++) {
        int kb = k4 * 4;
        float4 v = ar[k4];
        acc += v.x * wT[(kb + 0) * OUTC + f];
        acc += v.y * wT[(kb + 1) * OUTC + f];
        acc += v.z * wT[(kb + 2) * OUTC + f];
        acc += v.w * wT[(kb + 3) * OUTC + f];
    }
    g_h2[(nb + local) * OUTC + f] = acc;
    ps[local * OUTC + f] = acc * as_w[f];
    pd[local * OUTC + f] = acc * ad_w[f];
    __syncthreads();

    if (t < 16) {
        int node = t & 7;
        const float* p = (t < 8) ? (ps + node * OUTC) : (pd + node * OUTC);
        float s = 0.f;
        #pragma unroll
        for (int i = 0; i < OUTC; i++) s += p[i];
        if (t < 8) g_as2[nb + node] = s;
        else       g_ad2[nb + node] = s;
    }
}

// ---- layer-2 aggregation: warp/node, float2 lanes (l<20), 4-way unroll ----
__global__ void __launch_bounds__(256, 5) k_agg2(const float* __restrict__ b2,
                                                 float* __restrict__ out) {
    const int n = blockIdx.x * 8 + (threadIdx.x >> 5);
    const int l = threadIdx.x & 31;
    const int start = g_rowptr[n], end = g_rowptr[n + 1];
    const float ad = g_ad2[n];
    const float2* __restrict__ H = (const float2*)g_h2;
    const bool act = (l < 20);
    const float2 zz = make_float2(0.f, 0.f);

    float accx = 0.f, accy = 0.f, den = 0.f;
    for (int eb = start; eb < end; eb += 32) {
        int m = end - eb; if (m > 32) m = 32;
        int s = 0; float ex = 0.f;
        if (l < m) {
            s = g_csr_src[eb + l];
            float v = g_as2[s] + ad;
            v = (v > 0.f) ? v : 0.2f * v;
            ex = __expf(v);
        }
        den += ex;
        #pragma unroll
        for (int j = 0; j < 32; j += 4) {
            if (j >= m) break;                    // coarse exit every 4 edges
            int   s0 = __shfl_sync(FULL, s,  j + 0);
            int   s1 = __shfl_sync(FULL, s,  j + 1);
            int   s2 = __shfl_sync(FULL, s,  j + 2);
            int   s3 = __shfl_sync(FULL, s,  j + 3);
            float e0 = __shfl_sync(FULL, ex, j + 0);
            float e1 = __shfl_sync(FULL, ex, j + 1);
            float e2 = __shfl_sync(FULL, ex, j + 2);
            float e3 = __shfl_sync(FULL, ex, j + 3);
            float2 r0 = act ? H[s0 * 20 + l] : zz;
            float2 r1 = act ? H[s1 * 20 + l] : zz;
            float2 r2 = act ? H[s2 * 20 + l] : zz;
            float2 r3 = act ? H[s3 * 20 + l] : zz;
            accx += e0 * r0.x + e1 * r1.x + e2 * r2.x + e3 * r3.x;
            accy += e0 * r0.y + e1 * r1.y + e2 * r2.y + e3 * r3.y;
        }
    }
    #pragma unroll
    for (int off = 1; off < 32; off <<= 1) den += __shfl_xor_sync(FULL, den, off);

    if (act) {
        float2 bb = ((const float2*)b2)[l];
        float2 r;
        r.x = accx / den + bb.x;
        r.y = accy / den + bb.y;
        ((float2*)out)[n * 20 + l] = r;
    }
}

extern "C" void kernel_launch(void* const* d_in, const int* in_sizes, int n_in,
                              void* d_out, int out_size) {
    const float* x   = (const float*)d_in[0];
    const int*   ei  = (const int*)  d_in[1];
    const float* W1  = (const float*)d_in[2];
    const float* as1 = (const float*)d_in[3];
    const float* ad1 = (const float*)d_in[4];
    const float* b1  = (const float*)d_in[5];
    const float* W2  = (const float*)d_in[6];
    const float* as2 = (const float*)d_in[7];
    const float* ad2 = (const float*)d_in[8];
    const float* b2  = (const float*)d_in[9];
    float* out = (float*)d_out;

    int nE = in_sizes[1] / 2;
    const int* src = ei;
    const int* dst = ei + nE;

    const int T = 256;
    int eg = (nE + T - 1) / T;

    static cudaStream_t s2 = nullptr;
    static cudaEvent_t evFork = nullptr, evJoin = nullptr;
    if (s2 == nullptr) {
        cudaStreamCreateWithFlags(&s2, cudaStreamNonBlocking);
        cudaEventCreateWithFlags(&evFork, cudaEventDisableTiming);
        cudaEventCreateWithFlags(&evJoin, cudaEventDisableTiming);
    }

    cudaEventRecord(evFork, 0);
    cudaStreamWaitEvent(s2, evFork, 0);
    k_gemm1<<<NN / 16, 256, 0, s2>>>(x, W1, as1, ad1);
    cudaEventRecord(evJoin, s2);

    k_init <<<(NN + T - 1) / T, T>>>();
    k_hist <<<eg, T>>>(dst, nE);
    k_scanA<<<SCANB, 1024>>>();
    k_scanB<<<1, 128>>>();
    k_scanC<<<SCANB, 1024>>>();
    k_fill <<<eg, T>>>(src, dst, nE);

    cudaStreamWaitEvent(0, evJoin, 0);

    k_agg1 <<<NN / 8, 256>>>(b1);
    k_gemm2<<<NN / 8, 320>>>(W2, as2, ad2);
    k_agg2 <<<NN / 8, 256>>>(b2, out);
}